// round 3
// baseline (speedup 1.0000x reference)
#include <cuda_runtime.h>
#include <cstddef>

#define BB      64
#define NOTES   78
#define TT      128
#define IN_DIM  80
#define HID     64
#define G4      256   // 4*HID
#define NHID    2
#define NG      8     // 4*NHID
#define NSEQ    (BB * NOTES)        // 4992
#define NROW2   (BB * TT * NOTES)   // 638976 rows for note-proj... (see B1)

// ---------------- scratch (device globals; no allocation at runtime) ---------
// time-LSTM hidden outputs, [b][t][note][h]  (= [s2][note][h], s2 = b*TT+t)
__device__ float g_time_out[(size_t)BB * TT * NOTES * HID];
// precomputed input projection for time LSTM: [seq][t][256]
__device__ float g_gx[(size_t)NSEQ * TT * G4];
// precomputed input projection for note LSTM: [s2*NOTES + note][8]
__device__ float g_gxn[(size_t)BB * TT * NOTES * NG];

// ---------------- packed f32x2 helpers ----------------
typedef unsigned long long u64;
__device__ __forceinline__ u64 ffma2(u64 a, u64 b, u64 c) {
    u64 d;
    asm("fma.rn.f32x2 %0, %1, %2, %3;" : "=l"(d) : "l"(a), "l"(b), "l"(c));
    return d;
}
__device__ __forceinline__ u64 pk2(float lo, float hi) {
    u64 r;
    asm("mov.b64 %0, {%1, %2};" : "=l"(r) : "f"(lo), "f"(hi));
    return r;
}
__device__ __forceinline__ float2 up2(u64 a) {
    float2 v;
    asm("mov.b64 {%0, %1}, %2;" : "=f"(v.x), "=f"(v.y) : "l"(a));
    return v;
}
__device__ __forceinline__ float sigm(float v) { return 1.0f / (1.0f + expf(-v)); }

// ======================================================================
// Pass 1: gx[seq][t][j] = sum_d x[seq][t][d]*w_ih[j][d] + b_ih[j] + b_hh[j]
// CTA = 2 sequences, 256 threads; thread (s=tid>>7, jj=tid&127) owns gate
// rows 2jj, 2jj+1 with weights in registers. x staged per 64-step tile.
// ======================================================================
__global__ void __launch_bounds__(256, 1) gx_kernel(
    const float* __restrict__ x,
    const float* __restrict__ w_ih,
    const float* __restrict__ b_ih,
    const float* __restrict__ b_hh)
{
    __shared__ __align__(16) float x_sh[2 * 64 * IN_DIM];   // 40 KB

    const int tid = threadIdx.x;
    const int s   = tid >> 7;
    const int jj  = tid & 127;
    const int r0  = 2 * jj;
    const int seq0 = blockIdx.x * 2;

    // weights for 2 gate rows -> registers
    u64 w0[IN_DIM / 2], w1[IN_DIM / 2];
    {
        const u64* p0 = (const u64*)(w_ih + (size_t)r0 * IN_DIM);
        const u64* p1 = (const u64*)(w_ih + (size_t)(r0 + 1) * IN_DIM);
        #pragma unroll
        for (int d = 0; d < IN_DIM / 2; d++) { w0[d] = p0[d]; w1[d] = p1[d]; }
    }
    const float bias0 = b_ih[r0] + b_hh[r0];
    const float bias1 = b_ih[r0 + 1] + b_hh[r0 + 1];

    for (int tile = 0; tile < 2; tile++) {
        __syncthreads();
        // stage x for both sequences, 64 steps (2*64*80 floats = 2560 float4)
        {
            float4* xs = (float4*)x_sh;
            for (int i = tid; i < 2560; i += 256) {
                int ss  = i / 1280;
                int off = i - ss * 1280;
                const float4* xg = (const float4*)(x + ((size_t)(seq0 + ss) * TT + tile * 64) * IN_DIM);
                xs[ss * 1280 + off] = xg[off];
            }
        }
        __syncthreads();

        #pragma unroll 1
        for (int tt = 0; tt < 64; tt++) {
            const u64* xr = (const u64*)(x_sh + (s * 64 + tt) * IN_DIM);
            u64 a00 = pk2(0.f, 0.f), a01 = a00, a10 = a00, a11 = a00;
            #pragma unroll
            for (int d = 0; d < 20; d++) {
                u64 xv0 = xr[d], xv1 = xr[d + 20];
                a00 = ffma2(xv0, w0[d], a00);
                a10 = ffma2(xv0, w1[d], a10);
                a01 = ffma2(xv1, w0[d + 20], a01);
                a11 = ffma2(xv1, w1[d + 20], a11);
            }
            float2 v00 = up2(a00), v01 = up2(a01), v10 = up2(a10), v11 = up2(a11);
            float g0 = (v00.x + v00.y) + (v01.x + v01.y) + bias0;
            float g1 = (v10.x + v10.y) + (v11.x + v11.y) + bias1;
            int t = tile * 64 + tt;
            float2* gp = (float2*)(g_gx + ((size_t)(seq0 + s) * TT + t) * G4 + r0);
            *gp = make_float2(g0, g1);
        }
    }
}

// ======================================================================
// Pass 2: time-LSTM recurrence only. CTA = 2 sequences, 256 threads;
// thread (s, jj) owns gate rows 2jj, 2jj+1. gx prefetched 2 steps ahead.
// ======================================================================
__global__ void __launch_bounds__(256, 1) time_rec_kernel(
    const float* __restrict__ w_hh)
{
    __shared__ __align__(16) float h_sh[2][HID];
    __shared__ __align__(16) float gates[2][G4];

    const int tid = threadIdx.x;
    const int s   = tid >> 7;
    const int jj  = tid & 127;
    const int r0  = 2 * jj;
    const int seq = blockIdx.x * 2 + s;
    const int b    = seq / NOTES;
    const int note = seq % NOTES;
    const int klass = jj >> 5;     // 0:i 1:f 2:g 3:o (both rows same class)

    u64 w0[HID / 2], w1[HID / 2];
    {
        const u64* p0 = (const u64*)(w_hh + (size_t)r0 * HID);
        const u64* p1 = (const u64*)(w_hh + (size_t)(r0 + 1) * HID);
        #pragma unroll
        for (int k = 0; k < HID / 2; k++) { w0[k] = p0[k]; w1[k] = p1[k]; }
    }

    if (jj < HID) h_sh[s][jj] = 0.0f;
    float c = 0.0f;

    const float2* gxp = (const float2*)(g_gx + (size_t)seq * TT * G4 + r0);
    // prefetch gx for t=0,1  (stride per step = G4/2 float2)
    float2 gq0 = __ldg(gxp);
    float2 gq1 = __ldg(gxp + (G4 / 2));

    float* outb = g_time_out + ((size_t)b * TT * NOTES + note) * HID;

    __syncthreads();

    #pragma unroll 1
    for (int t = 0; t < TT; t++) {
        float2 gcur = (t & 1) ? gq1 : gq0;
        // prefetch t+2
        if (t + 2 < TT) {
            float2 nv = __ldg(gxp + (size_t)(t + 2) * (G4 / 2));
            if (t & 1) gq1 = nv; else gq0 = nv;
        }

        const u64* hr = (const u64*)h_sh[s];
        u64 a00 = pk2(0.f, 0.f), a01 = a00, a10 = a00, a11 = a00;
        #pragma unroll
        for (int k = 0; k < 16; k++) {
            u64 hv0 = hr[k], hv1 = hr[k + 16];
            a00 = ffma2(hv0, w0[k], a00);
            a10 = ffma2(hv0, w1[k], a10);
            a01 = ffma2(hv1, w0[k + 16], a01);
            a11 = ffma2(hv1, w1[k + 16], a11);
        }
        float2 v00 = up2(a00), v01 = up2(a01), v10 = up2(a10), v11 = up2(a11);
        float g0 = (v00.x + v00.y) + (v01.x + v01.y) + gcur.x;
        float g1 = (v10.x + v10.y) + (v11.x + v11.y) + gcur.y;

        float act0, act1;
        if (klass == 2) { act0 = tanhf(g0); act1 = tanhf(g1); }
        else            { act0 = sigm(g0);  act1 = sigm(g1); }
        *(float2*)&gates[s][r0] = make_float2(act0, act1);
        __syncthreads();

        if (jj < HID) {
            const int u = jj;
            float iv = gates[s][u];
            float fv = gates[s][64 + u];
            float gv = gates[s][128 + u];
            float ov = gates[s][192 + u];
            c = fv * c + iv * gv;
            float h = ov * tanhf(c);
            h_sh[s][u] = h;
            outb[(size_t)t * NOTES * HID + u] = h;
        }
        __syncthreads();
    }
}

// ======================================================================
// Pass B1: note-LSTM input projection.
// gxn[r][jg] = sum_k time_out_row[r][k]*w_ih_n[jg][k] + b_ih_n + b_hh_n
// r enumerates (s2, note) contiguously. 2 rows per thread, weights in SMEM.
// ======================================================================
__global__ void __launch_bounds__(256, 1) gxn_kernel(
    const float* __restrict__ w_ih,
    const float* __restrict__ b_ih,
    const float* __restrict__ b_hh)
{
    __shared__ __align__(16) float wshf[NG * HID];
    __shared__ float bsh[NG];

    const int tid = threadIdx.x;
    for (int i = tid; i < NG * HID; i += 256) wshf[i] = w_ih[i];
    if (tid < NG) bsh[tid] = b_ih[tid] + b_hh[tid];
    __syncthreads();

    const u64* wsh = (const u64*)wshf;    // [jg*32 + k]

    const size_t r2 = (size_t)blockIdx.x * 256 + tid;   // 0 .. 319487
    const size_t r0 = 2 * r2;

    // load 2 rows (64 floats each) into registers
    u64 x0[32], x1[32];
    {
        const u64* p0 = (const u64*)(g_time_out + r0 * HID);
        const u64* p1 = (const u64*)(g_time_out + (r0 + 1) * HID);
        #pragma unroll
        for (int k = 0; k < 32; k++) { x0[k] = p0[k]; x1[k] = p1[k]; }
    }

    u64 ac0[NG], ac1[NG];
    #pragma unroll
    for (int jg = 0; jg < NG; jg++) { ac0[jg] = pk2(0.f, 0.f); ac1[jg] = pk2(0.f, 0.f); }

    #pragma unroll
    for (int k = 0; k < 32; k++) {
        #pragma unroll
        for (int jg = 0; jg < NG; jg++) {
            u64 wv = wsh[jg * 32 + k];
            ac0[jg] = ffma2(x0[k], wv, ac0[jg]);
            ac1[jg] = ffma2(x1[k], wv, ac1[jg]);
        }
    }

    float o0[NG], o1[NG];
    #pragma unroll
    for (int jg = 0; jg < NG; jg++) {
        float2 v0 = up2(ac0[jg]), v1 = up2(ac1[jg]);
        o0[jg] = v0.x + v0.y + bsh[jg];
        o1[jg] = v1.x + v1.y + bsh[jg];
    }
    float4* gp = (float4*)(g_gxn + r0 * NG);
    gp[0] = make_float4(o0[0], o0[1], o0[2], o0[3]);
    gp[1] = make_float4(o0[4], o0[5], o0[6], o0[7]);
    gp[2] = make_float4(o1[0], o1[1], o1[2], o1[3]);
    gp[3] = make_float4(o1[4], o1[5], o1[6], o1[7]);
}

// ======================================================================
// Pass B2: note-LSTM recurrence (hidden=2), one thread per (b,t).
// Only 16 FMAs + activations per note step; gxn prefetched 2 notes ahead.
// ======================================================================
__global__ void __launch_bounds__(128) note_rec_kernel(
    const float* __restrict__ w_hh,
    float* __restrict__ out)
{
    __shared__ float whhsh[NG * NHID];
    const int tid = threadIdx.x;
    if (tid < NG * NHID) whhsh[tid] = w_hh[tid];
    __syncthreads();

    float wr[NG * NHID];
    #pragma unroll
    for (int i = 0; i < NG * NHID; i++) wr[i] = whhsh[i];

    const int s2 = blockIdx.x * 128 + tid;   // 0 .. 8191
    const float4* gp = (const float4*)(g_gxn + (size_t)s2 * NOTES * NG);
    float* op = out + (size_t)s2 * NOTES * NHID;

    float h0 = 0.f, h1 = 0.f, c0 = 0.f, c1 = 0.f;

    // prefetch notes 0,1  (2 float4 per note)
    float4 pa0 = __ldg(gp + 0), pb0 = __ldg(gp + 1);
    float4 pa1 = __ldg(gp + 2), pb1 = __ldg(gp + 3);

    #pragma unroll 1
    for (int note = 0; note < NOTES; note++) {
        float4 qa = (note & 1) ? pa1 : pa0;
        float4 qb = (note & 1) ? pb1 : pb0;
        if (note + 2 < NOTES) {
            float4 na = __ldg(gp + (note + 2) * 2);
            float4 nb = __ldg(gp + (note + 2) * 2 + 1);
            if (note & 1) { pa1 = na; pb1 = nb; } else { pa0 = na; pb0 = nb; }
        }

        float acc0 = qa.x + h0 * wr[0]  + h1 * wr[1];   // i0
        float acc1 = qa.y + h0 * wr[2]  + h1 * wr[3];   // i1
        float acc2 = qa.z + h0 * wr[4]  + h1 * wr[5];   // f0
        float acc3 = qa.w + h0 * wr[6]  + h1 * wr[7];   // f1
        float acc4 = qb.x + h0 * wr[8]  + h1 * wr[9];   // g0
        float acc5 = qb.y + h0 * wr[10] + h1 * wr[11];  // g1
        float acc6 = qb.z + h0 * wr[12] + h1 * wr[13];  // o0
        float acc7 = qb.w + h0 * wr[14] + h1 * wr[15];  // o1

        float i0 = sigm(acc0),  i1 = sigm(acc1);
        float f0 = sigm(acc2),  f1 = sigm(acc3);
        float g0 = tanhf(acc4), g1 = tanhf(acc5);
        float o0v = sigm(acc6), o1v = sigm(acc7);
        c0 = f0 * c0 + i0 * g0;
        c1 = f1 * c1 + i1 * g1;
        h0 = o0v * tanhf(c0);
        h1 = o1v * tanhf(c1);

        op[note * 2 + 0] = (h0 > 0.5f) ? 1.0f : 0.0f;
        op[note * 2 + 1] = (h1 > 0.5f) ? 1.0f : 0.0f;
    }
}

// ======================================================================
extern "C" void kernel_launch(void* const* d_in, const int* in_sizes, int n_in,
                              void* d_out, int out_size)
{
    const float* x      = (const float*)d_in[0];
    const float* w_ih_t = (const float*)d_in[1];
    const float* w_hh_t = (const float*)d_in[2];
    const float* b_ih_t = (const float*)d_in[3];
    const float* b_hh_t = (const float*)d_in[4];
    const float* w_ih_n = (const float*)d_in[5];
    const float* w_hh_n = (const float*)d_in[6];
    const float* b_ih_n = (const float*)d_in[7];
    const float* b_hh_n = (const float*)d_in[8];

    gx_kernel<<<NSEQ / 2, 256>>>(x, w_ih_t, b_ih_t, b_hh_t);
    time_rec_kernel<<<NSEQ / 2, 256>>>(w_hh_t);
    gxn_kernel<<<(BB * TT * NOTES) / 512, 256>>>(w_ih_n, b_ih_n, b_hh_n);
    note_rec_kernel<<<BB * TT / 128, 128>>>(w_hh_n, (float*)d_out);
}

// round 4
// speedup vs baseline: 1.3018x; 1.3018x over previous
#include <cuda_runtime.h>
#include <cstddef>

#define BB      64
#define NOTES   78
#define TT      128
#define IN_DIM  80
#define HID     64
#define G4      256
#define NHID    2
#define NG      8
#define NSEQ    (BB * NOTES)          // 4992
#define MROWS   (NSEQ * TT)           // 638976

// scratch (device globals, no runtime allocation)
__device__ float g_gx[(size_t)MROWS * G4];                 // [seq*TT + t][256]
__device__ float g_gxn[(size_t)BB * TT * NOTES * NG];      // [(b*TT+t)*NOTES + note][8]

typedef unsigned long long u64;
__device__ __forceinline__ u64 ffma2(u64 a, u64 b, u64 c) {
    u64 d;
    asm("fma.rn.f32x2 %0, %1, %2, %3;" : "=l"(d) : "l"(a), "l"(b), "l"(c));
    return d;
}
__device__ __forceinline__ u64 pk2(float lo, float hi) {
    u64 r;
    asm("mov.b64 %0, {%1, %2};" : "=l"(r) : "f"(lo), "f"(hi));
    return r;
}
__device__ __forceinline__ float2 up2(u64 a) {
    float2 v;
    asm("mov.b64 {%0, %1}, %2;" : "=f"(v.x), "=f"(v.y) : "l"(a));
    return v;
}
__device__ __forceinline__ float sigm(float v) { return 1.0f / (1.0f + expf(-v)); }

// ======================================================================
// gx SGEMM: g_gx[r][n] = sum_d x[r][d] * w_ih[n][d] + b_ih[n] + b_hh[n]
// CTA tile 128M x 128N, K=80 in two 40-chunks. Thread tile 8M x 8N.
// smem staged TRANSPOSED ([k][m], [k][n]) -> conflict-free STS.32 stores,
// broadcast/sequential LDS.128 loads, x m-pairs come pre-packed for f32x2.
// ======================================================================
__global__ void __launch_bounds__(256, 2) gx_kernel(
    const float* __restrict__ x,
    const float* __restrict__ w_ih,
    const float* __restrict__ b_ih,
    const float* __restrict__ b_hh)
{
    __shared__ __align__(16) float xT[40][128];
    __shared__ __align__(16) float wT[40][128];

    const int tid = threadIdx.x;
    const int tx = tid & 15;          // n-block 0..15
    const int ty = tid >> 4;          // m-block 0..15
    const size_t r0 = (size_t)blockIdx.x * 128;
    const int n0 = blockIdx.y * 128;

    u64 acc[4][8];
    #pragma unroll
    for (int mp = 0; mp < 4; mp++)
        #pragma unroll
        for (int n = 0; n < 8; n++) acc[mp][n] = pk2(0.f, 0.f);

    float bia[8];
    #pragma unroll
    for (int i = 0; i < 8; i++) {
        int n = n0 + tx * 8 + i;
        bia[i] = b_ih[n] + b_hh[n];
    }

    const float4* xg = (const float4*)x;      // [r][20]
    const float4* wg = (const float4*)w_ih;   // [n][20]

    for (int c = 0; c < 2; c++) {
        __syncthreads();
        #pragma unroll
        for (int it = 0; it < 5; it++) {
            int idx = tid + it * 256;         // 0..1279
            int kq = idx >> 7;                // 0..9
            int m  = idx & 127;
            float4 xv = xg[(r0 + m) * 20 + c * 10 + kq];
            xT[kq * 4 + 0][m] = xv.x; xT[kq * 4 + 1][m] = xv.y;
            xT[kq * 4 + 2][m] = xv.z; xT[kq * 4 + 3][m] = xv.w;
            float4 wv = wg[(size_t)(n0 + m) * 20 + c * 10 + kq];
            wT[kq * 4 + 0][m] = wv.x; wT[kq * 4 + 1][m] = wv.y;
            wT[kq * 4 + 2][m] = wv.z; wT[kq * 4 + 3][m] = wv.w;
        }
        __syncthreads();

        #pragma unroll
        for (int k = 0; k < 40; k++) {
            const float4* xr = (const float4*)xT[k];
            const float4* wr = (const float4*)wT[k];
            float4 xa = xr[ty * 2], xb = xr[ty * 2 + 1];
            float4 wa = wr[tx * 2], wb = wr[tx * 2 + 1];
            u64 xp[4];
            xp[0] = pk2(xa.x, xa.y); xp[1] = pk2(xa.z, xa.w);
            xp[2] = pk2(xb.x, xb.y); xp[3] = pk2(xb.z, xb.w);
            u64 wd[8];
            wd[0] = pk2(wa.x, wa.x); wd[1] = pk2(wa.y, wa.y);
            wd[2] = pk2(wa.z, wa.z); wd[3] = pk2(wa.w, wa.w);
            wd[4] = pk2(wb.x, wb.x); wd[5] = pk2(wb.y, wb.y);
            wd[6] = pk2(wb.z, wb.z); wd[7] = pk2(wb.w, wb.w);
            #pragma unroll
            for (int mp = 0; mp < 4; mp++)
                #pragma unroll
                for (int n = 0; n < 8; n++)
                    acc[mp][n] = ffma2(xp[mp], wd[n], acc[mp][n]);
        }
    }

    // epilogue: unpack m-pairs, add bias, coalesced float4 stores
    #pragma unroll
    for (int mp = 0; mp < 4; mp++) {
        float lo[8], hi[8];
        #pragma unroll
        for (int n = 0; n < 8; n++) {
            float2 v = up2(acc[mp][n]);
            lo[n] = v.x + bia[n];
            hi[n] = v.y + bia[n];
        }
        float* o0 = g_gx + (r0 + ty * 8 + mp * 2) * G4 + n0 + tx * 8;
        ((float4*)o0)[0] = make_float4(lo[0], lo[1], lo[2], lo[3]);
        ((float4*)o0)[1] = make_float4(lo[4], lo[5], lo[6], lo[7]);
        float* o1 = o0 + G4;
        ((float4*)o1)[0] = make_float4(hi[0], hi[1], hi[2], hi[3]);
        ((float4*)o1)[1] = make_float4(hi[4], hi[5], hi[6], hi[7]);
    }
}

// ======================================================================
// time-LSTM recurrence, 2 seqs/CTA, 1 gate-row per thread (serves both
// seqs, weights in 64 regs). gxn (note-LSTM input projection) fused:
// threads 128..143 compute it for step t-1 overlapped with step t.
// ======================================================================
__global__ void __launch_bounds__(256, 2) time_rec_kernel(
    const float* __restrict__ w_hh,
    const float* __restrict__ w_ih_n,
    const float* __restrict__ b_ih_n,
    const float* __restrict__ b_hh_n)
{
    __shared__ __align__(16) float h_sh[2][HID];
    __shared__ __align__(16) float gates[2][G4];
    __shared__ __align__(16) float wn_sh[NG][HID];
    __shared__ float bn_sh[NG];

    const int jj = threadIdx.x;
    const int seq0 = blockIdx.x * 2;
    const int klass = jj >> 6;            // 0:i 1:f 2:g 3:o

    u64 w[32];
    {
        const u64* p = (const u64*)(w_hh + (size_t)jj * HID);
        #pragma unroll
        for (int k = 0; k < 32; k++) w[k] = p[k];
    }
    for (int i = jj; i < NG * HID; i += 256) wn_sh[i >> 6][i & 63] = w_ih_n[i];
    if (jj < NG) bn_sh[jj] = b_ih_n[jj] + b_hh_n[jj];
    if (jj < 2 * HID) h_sh[jj >> 6][jj & 63] = 0.0f;
    float c = 0.0f;

    const float* gxa = g_gx + (size_t)seq0 * TT * G4 + jj;
    const float* gxb = gxa + (size_t)TT * G4;
    float p00 = __ldg(gxa), p01 = __ldg(gxa + G4);
    float p10 = __ldg(gxb), p11 = __ldg(gxb + G4);

    // gxn output bases per seq
    size_t gxn_base[2];
    #pragma unroll
    for (int s = 0; s < 2; s++) {
        int seq = seq0 + s;
        int b_ = seq / NOTES, note = seq % NOTES;
        gxn_base[s] = (((size_t)b_ * TT) * NOTES + note) * NG;  // + t*NOTES*NG
    }

    __syncthreads();

    #pragma unroll 1
    for (int t = 0; t < TT; t++) {
        float g0 = (t & 1) ? p01 : p00;
        float g1 = (t & 1) ? p11 : p10;
        if (t + 2 < TT) {
            float n0 = __ldg(gxa + (size_t)(t + 2) * G4);
            float n1 = __ldg(gxb + (size_t)(t + 2) * G4);
            if (t & 1) { p01 = n0; p11 = n1; } else { p00 = n0; p10 = n1; }
        }

        // fused gxn for step t-1 (h_sh currently holds h(t-1))
        if (t > 0 && jj >= 128 && jj < 144) {
            int q = jj - 128, s = q >> 3, jg = q & 7;
            const float4* hp = (const float4*)h_sh[s];
            const float4* wp = (const float4*)wn_sh[jg];
            float dot = bn_sh[jg];
            #pragma unroll
            for (int i = 0; i < 16; i++) {
                float4 a = hp[i], b = wp[i];
                dot += a.x * b.x + a.y * b.y + a.z * b.z + a.w * b.w;
            }
            g_gxn[gxn_base[s] + (size_t)(t - 1) * NOTES * NG + jg] = dot;
        }

        // gate GEMV for both seqs (f32x2, h pre-packed via LDS.128)
        const float4* h0 = (const float4*)h_sh[0];
        const float4* h1 = (const float4*)h_sh[1];
        u64 a00 = pk2(0.f, 0.f), a01 = a00, a10 = a00, a11 = a00;
        #pragma unroll
        for (int k = 0; k < 8; k++) {
            float4 ha = h0[k], hb = h0[k + 8];
            float4 hc = h1[k], hd = h1[k + 8];
            a00 = ffma2(pk2(ha.x, ha.y), w[2 * k], a00);
            a00 = ffma2(pk2(ha.z, ha.w), w[2 * k + 1], a00);
            a01 = ffma2(pk2(hb.x, hb.y), w[16 + 2 * k], a01);
            a01 = ffma2(pk2(hb.z, hb.w), w[16 + 2 * k + 1], a01);
            a10 = ffma2(pk2(hc.x, hc.y), w[2 * k], a10);
            a10 = ffma2(pk2(hc.z, hc.w), w[2 * k + 1], a10);
            a11 = ffma2(pk2(hd.x, hd.y), w[16 + 2 * k], a11);
            a11 = ffma2(pk2(hd.z, hd.w), w[16 + 2 * k + 1], a11);
        }
        float2 v00 = up2(a00), v01 = up2(a01), v10 = up2(a10), v11 = up2(a11);
        float s0 = (v00.x + v00.y) + (v01.x + v01.y) + g0;
        float s1 = (v10.x + v10.y) + (v11.x + v11.y) + g1;

        float act0, act1;
        if (klass == 2) { act0 = tanhf(s0); act1 = tanhf(s1); }
        else            { act0 = sigm(s0);  act1 = sigm(s1); }
        gates[0][jj] = act0;
        gates[1][jj] = act1;
        __syncthreads();

        if (jj < 128) {
            int s = jj >> 6, u = jj & 63;
            float iv = gates[s][u];
            float fv = gates[s][64 + u];
            float gv = gates[s][128 + u];
            float ov = gates[s][192 + u];
            c = fv * c + iv * gv;
            h_sh[s][u] = ov * tanhf(c);
        }
        __syncthreads();
    }

    // gxn for the final step (h(127))
    if (jj >= 128 && jj < 144) {
        int q = jj - 128, s = q >> 3, jg = q & 7;
        const float4* hp = (const float4*)h_sh[s];
        const float4* wp = (const float4*)wn_sh[jg];
        float dot = bn_sh[jg];
        #pragma unroll
        for (int i = 0; i < 16; i++) {
            float4 a = hp[i], b = wp[i];
            dot += a.x * b.x + a.y * b.y + a.z * b.z + a.w * b.w;
        }
        g_gxn[gxn_base[s] + (size_t)(TT - 1) * NOTES * NG + jg] = dot;
    }
}

// ======================================================================
// note-LSTM recurrence (hidden=2). 2 independent chains per thread for
// latency hiding (it's a pure serial-latency kernel at 55 thr/SM).
// ======================================================================
__global__ void __launch_bounds__(128) note_rec_kernel(
    const float* __restrict__ w_hh,
    float* __restrict__ out)
{
    float wr[NG * NHID];
    #pragma unroll
    for (int i = 0; i < NG * NHID; i++) wr[i] = __ldg(w_hh + i);

    const int gid = blockIdx.x * 128 + threadIdx.x;   // 0..4095
    const int sA = gid, sB = gid + 4096;

    const float4* gA = (const float4*)(g_gxn + (size_t)sA * NOTES * NG);
    const float4* gB = (const float4*)(g_gxn + (size_t)sB * NOTES * NG);
    float* oA = out + (size_t)sA * NOTES * NHID;
    float* oB = out + (size_t)sB * NOTES * NHID;

    float hA0 = 0.f, hA1 = 0.f, cA0 = 0.f, cA1 = 0.f;
    float hB0 = 0.f, hB1 = 0.f, cB0 = 0.f, cB1 = 0.f;

    float4 qaA = __ldg(gA + 0), qbA = __ldg(gA + 1);
    float4 qaB = __ldg(gB + 0), qbB = __ldg(gB + 1);

    #pragma unroll 1
    for (int note = 0; note < NOTES; note++) {
        float4 aA = qaA, bA = qbA, aB = qaB, bB = qbB;
        if (note + 1 < NOTES) {
            qaA = __ldg(gA + (note + 1) * 2);
            qbA = __ldg(gA + (note + 1) * 2 + 1);
            qaB = __ldg(gB + (note + 1) * 2);
            qbB = __ldg(gB + (note + 1) * 2 + 1);
        }

        float A0 = aA.x + hA0 * wr[0]  + hA1 * wr[1];
        float A1 = aA.y + hA0 * wr[2]  + hA1 * wr[3];
        float A2 = aA.z + hA0 * wr[4]  + hA1 * wr[5];
        float A3 = aA.w + hA0 * wr[6]  + hA1 * wr[7];
        float A4 = bA.x + hA0 * wr[8]  + hA1 * wr[9];
        float A5 = bA.y + hA0 * wr[10] + hA1 * wr[11];
        float A6 = bA.z + hA0 * wr[12] + hA1 * wr[13];
        float A7 = bA.w + hA0 * wr[14] + hA1 * wr[15];

        float B0 = aB.x + hB0 * wr[0]  + hB1 * wr[1];
        float B1 = aB.y + hB0 * wr[2]  + hB1 * wr[3];
        float B2 = aB.z + hB0 * wr[4]  + hB1 * wr[5];
        float B3 = aB.w + hB0 * wr[6]  + hB1 * wr[7];
        float B4 = bB.x + hB0 * wr[8]  + hB1 * wr[9];
        float B5 = bB.y + hB0 * wr[10] + hB1 * wr[11];
        float B6 = bB.z + hB0 * wr[12] + hB1 * wr[13];
        float B7 = bB.w + hB0 * wr[14] + hB1 * wr[15];

        float iA0 = sigm(A0),  iA1 = sigm(A1);
        float fA0 = sigm(A2),  fA1 = sigm(A3);
        float gA0 = tanhf(A4), gA1 = tanhf(A5);
        float oA0 = sigm(A6),  oA1 = sigm(A7);
        float iB0 = sigm(B0),  iB1 = sigm(B1);
        float fB0 = sigm(B2),  fB1 = sigm(B3);
        float gB0 = tanhf(B4), gB1 = tanhf(B5);
        float oB0 = sigm(B6),  oB1 = sigm(B7);

        cA0 = fA0 * cA0 + iA0 * gA0;
        cA1 = fA1 * cA1 + iA1 * gA1;
        cB0 = fB0 * cB0 + iB0 * gB0;
        cB1 = fB1 * cB1 + iB1 * gB1;
        hA0 = oA0 * tanhf(cA0);
        hA1 = oA1 * tanhf(cA1);
        hB0 = oB0 * tanhf(cB0);
        hB1 = oB1 * tanhf(cB1);

        oA[note * 2 + 0] = (hA0 > 0.5f) ? 1.0f : 0.0f;
        oA[note * 2 + 1] = (hA1 > 0.5f) ? 1.0f : 0.0f;
        oB[note * 2 + 0] = (hB0 > 0.5f) ? 1.0f : 0.0f;
        oB[note * 2 + 1] = (hB1 > 0.5f) ? 1.0f : 0.0f;
    }
}

// ======================================================================
extern "C" void kernel_launch(void* const* d_in, const int* in_sizes, int n_in,
                              void* d_out, int out_size)
{
    const float* x      = (const float*)d_in[0];
    const float* w_ih_t = (const float*)d_in[1];
    const float* w_hh_t = (const float*)d_in[2];
    const float* b_ih_t = (const float*)d_in[3];
    const float* b_hh_t = (const float*)d_in[4];
    const float* w_ih_n = (const float*)d_in[5];
    const float* w_hh_n = (const float*)d_in[6];
    const float* b_ih_n = (const float*)d_in[7];
    const float* b_hh_n = (const float*)d_in[8];

    gx_kernel<<<dim3(MROWS / 128, 2), 256>>>(x, w_ih_t, b_ih_t, b_hh_t);
    time_rec_kernel<<<NSEQ / 2, 256>>>(w_hh_t, w_ih_n, b_ih_n, b_hh_n);
    note_rec_kernel<<<32, 128>>>(w_hh_n, (float*)d_out);
}